// round 4
// baseline (speedup 1.0000x reference)
#include <cuda_runtime.h>
#include <math.h>

// ---------------------------------------------------------------------------
// VoxelBackBone8x decoder: 8 x (gather-GEMM over 27 taps + BN + relu)
// Strategy:
//   * One templated tile kernel: TN rows x CO cols per block, loop over taps.
//   * Per-(tile,tap) skip when no row in the tile has a valid neighbor
//     (sparse voxel grids: deep levels have ~1-3 live taps of 27).
//   * BN applied lazily: GEMM writes raw y + per-channel sum/sumsq stats;
//     tiny finalize kernel builds affine (a,b); next layer applies
//     relu(y*a+b) during its gather. Final layer normalized by output kernel.
//   * R3 fix: zero ALL 1024 stats entries every call (was zeroing only 256,
//     causing layers 2-7 stats to accumulate across graph replays).
// ---------------------------------------------------------------------------

#define MAXROWS 102400

__device__ float g_bufA[MAXROWS * 64];
__device__ float g_bufB[MAXROWS * 64];
__device__ float g_stats[8 * 2 * 64];   // per layer: [sum(64), sumsq(64)]
__device__ float g_aff[8 * 2 * 64];     // per layer: [a(64), b(64)]

__global__ void zero_stats_kernel() {
    int t = blockIdx.x * blockDim.x + threadIdx.x;
    if (t < 8 * 2 * 64) g_stats[t] = 0.f;
}

// stats: [sum(64), sumsq(64)] for one layer; aff out: [a(64), b(64)]
__global__ void finalize_kernel(const float* __restrict__ stats,
                                const float* __restrict__ g,
                                const float* __restrict__ b,
                                float* __restrict__ aff, int N, int CO) {
    int c = threadIdx.x;
    if (c < CO) {
        float invN = 1.0f / (float)N;
        float mu = stats[c] * invN;
        float var = stats[64 + c] * invN - mu * mu;
        float a = g[c] * rsqrtf(var + 1e-3f);
        aff[c] = a;
        aff[64 + c] = b[c] - mu * a;
    }
}

// final normalize (no relu): out[n,3] = y[n,3]*a + b
__global__ void output_kernel(const float* __restrict__ y,
                              const float* __restrict__ aff,
                              float* __restrict__ out, int total) {
    int i = blockIdx.x * blockDim.x + threadIdx.x;
    if (i < total) {
        int j = i % 3;
        out[i] = fmaf(y[i], aff[j], aff[64 + j]);
    }
}

// ---------------------------------------------------------------------------
// Gather-GEMM tile kernel.
//  CI: input channels, CO: output channels, COP: CO padded to mult of 4
//  TN: rows per tile, G: column groups (COP/4), RPT: rows per thread
//  APPLY: apply previous layer's affine+relu while gathering
// Thread layout: 256 threads, cg = tid % G owns cols [4cg,4cg+4),
//                rg = tid / G owns rows [rg*RPT, rg*RPT+RPT).
// ---------------------------------------------------------------------------
template <int CI, int CO, int COP, int TN, int G, int RPT, bool APPLY>
__launch_bounds__(256, 2)
__global__ void gemm_gather_kernel(const float* __restrict__ in,
                                   const int* __restrict__ nbr,
                                   const float* __restrict__ W,     // [27][CI][CO]
                                   const float* __restrict__ aff,   // [a(64), b(64)] or null
                                   float* __restrict__ out,         // [N][CO]
                                   float* __restrict__ stats,       // [sum(64), sumsq(64)]
                                   int N) {
    constexpr int CIP = CI + 4;   // padded row stride (floats), 16B-aligned, bank-skewed

    __shared__ float s_x[TN * CIP];
    __shared__ float s_w[CI * COP];
    __shared__ int   s_nbr[TN * 27];
    __shared__ int   s_flag[27];
    __shared__ float s_a[CI];
    __shared__ float s_b[CI];
    __shared__ float s_stats[2][COP];

    const int tid = threadIdx.x;
    const int rowbase = blockIdx.x * TN;

    if (tid < 27) s_flag[tid] = 0;
    if (tid < COP) { s_stats[0][tid] = 0.f; s_stats[1][tid] = 0.f; }
    if (APPLY) {
        for (int c = tid; c < CI; c += 256) {
            s_a[c] = aff[c];
            s_b[c] = aff[64 + c];
        }
    }
    __syncthreads();

    // stage neighbor tile + tap-live flags
    for (int i = tid; i < TN * 27; i += 256) {
        int r = i / 27;
        int k = i - r * 27;
        int gr = rowbase + r;
        int v = (gr < N) ? nbr[gr * 27 + k] : -1;
        s_nbr[i] = v;
        if (v >= 0) s_flag[k] = 1;
    }
    __syncthreads();

    const int cg = tid % G;
    const int rg = tid / G;
    const int r0 = rg * RPT;

    float acc[RPT][4];
#pragma unroll
    for (int i = 0; i < RPT; ++i)
#pragma unroll
        for (int j = 0; j < 4; ++j) acc[i][j] = 0.f;

    for (int k = 0; k < 27; ++k) {
        if (!s_flag[k]) continue;
        __syncthreads();   // protect s_w/s_x from previous tap's readers

        // stage W[k] (pad cols with 0 when CO != COP)
        if (CO == COP) {
            const float4* Wk = (const float4*)(W + (size_t)k * CI * CO);
            for (int v = tid; v < CI * CO / 4; v += 256)
                ((float4*)s_w)[v] = Wk[v];
        } else {
            const float* Wk = W + (size_t)k * CI * CO;
            for (int v = tid; v < CI * COP; v += 256) {
                int c = v / COP, j = v - c * COP;
                s_w[v] = (j < CO) ? Wk[c * CO + j] : 0.f;
            }
        }

        // gather features for this tap (apply prev affine + relu)
        for (int v = tid; v < TN * CI / 4; v += 256) {
            int r = v / (CI / 4);
            int c4 = v - r * (CI / 4);
            int idx = s_nbr[r * 27 + k];
            float4 val = make_float4(0.f, 0.f, 0.f, 0.f);
            if (idx >= 0) {
                val = *(const float4*)(in + (size_t)idx * CI + c4 * 4);
                if (APPLY) {
                    int c = c4 * 4;
                    val.x = fmaxf(fmaf(val.x, s_a[c + 0], s_b[c + 0]), 0.f);
                    val.y = fmaxf(fmaf(val.y, s_a[c + 1], s_b[c + 1]), 0.f);
                    val.z = fmaxf(fmaf(val.z, s_a[c + 2], s_b[c + 2]), 0.f);
                    val.w = fmaxf(fmaf(val.w, s_a[c + 3], s_b[c + 3]), 0.f);
                }
            }
            *(float4*)(s_x + r * CIP + c4 * 4) = val;
        }
        __syncthreads();

        // register-blocked FFMA: acc[i][j] += x[r0+i][c] * w[c][4cg+j]
#pragma unroll
        for (int c = 0; c < CI; c += 4) {
            float4 w0 = *(const float4*)(s_w + (c + 0) * COP + 4 * cg);
            float4 w1 = *(const float4*)(s_w + (c + 1) * COP + 4 * cg);
            float4 w2 = *(const float4*)(s_w + (c + 2) * COP + 4 * cg);
            float4 w3 = *(const float4*)(s_w + (c + 3) * COP + 4 * cg);
#pragma unroll
            for (int i = 0; i < RPT; ++i) {
                float4 xv = *(const float4*)(s_x + (r0 + i) * CIP + c);
                acc[i][0] = fmaf(xv.x, w0.x, acc[i][0]);
                acc[i][1] = fmaf(xv.x, w0.y, acc[i][1]);
                acc[i][2] = fmaf(xv.x, w0.z, acc[i][2]);
                acc[i][3] = fmaf(xv.x, w0.w, acc[i][3]);
                acc[i][0] = fmaf(xv.y, w1.x, acc[i][0]);
                acc[i][1] = fmaf(xv.y, w1.y, acc[i][1]);
                acc[i][2] = fmaf(xv.y, w1.z, acc[i][2]);
                acc[i][3] = fmaf(xv.y, w1.w, acc[i][3]);
                acc[i][0] = fmaf(xv.z, w2.x, acc[i][0]);
                acc[i][1] = fmaf(xv.z, w2.y, acc[i][1]);
                acc[i][2] = fmaf(xv.z, w2.z, acc[i][2]);
                acc[i][3] = fmaf(xv.z, w2.w, acc[i][3]);
                acc[i][0] = fmaf(xv.w, w3.x, acc[i][0]);
                acc[i][1] = fmaf(xv.w, w3.y, acc[i][1]);
                acc[i][2] = fmaf(xv.w, w3.z, acc[i][2]);
                acc[i][3] = fmaf(xv.w, w3.w, acc[i][3]);
            }
        }
    }

    // per-channel stats (only rows < N) + store raw y
#pragma unroll
    for (int j = 0; j < 4; ++j) {
        float s1 = 0.f, s2 = 0.f;
#pragma unroll
        for (int i = 0; i < RPT; ++i) {
            int gr = rowbase + r0 + i;
            if (gr < N) {
                float y = acc[i][j];
                s1 += y;
                s2 += y * y;
            }
        }
        atomicAdd(&s_stats[0][4 * cg + j], s1);
        atomicAdd(&s_stats[1][4 * cg + j], s2);
    }
#pragma unroll
    for (int i = 0; i < RPT; ++i) {
        int gr = rowbase + r0 + i;
        if (gr < N) {
            if (CO == COP) {
                *(float4*)(out + (size_t)gr * CO + 4 * cg) =
                    make_float4(acc[i][0], acc[i][1], acc[i][2], acc[i][3]);
            } else {  // CO==3 path: G==1, one thread per row
#pragma unroll
                for (int j = 0; j < CO; ++j)
                    out[(size_t)gr * CO + j] = acc[i][j];
            }
        }
    }
    __syncthreads();
    if (tid < CO) {
        atomicAdd(&stats[tid], s_stats[0][tid]);
        atomicAdd(&stats[64 + tid], s_stats[1][tid]);
    }
}

extern "C" void kernel_launch(void* const* d_in, const int* in_sizes, int n_in,
                              void* d_out, int out_size) {
    const int* nbr4  = (const int*)d_in[0];
    const int* inv43 = (const int*)d_in[1];
    const int* nbr3  = (const int*)d_in[2];
    const int* inv32 = (const int*)d_in[3];
    const int* nbr2  = (const int*)d_in[4];
    const int* inv21 = (const int*)d_in[5];
    const int* nbr1  = (const int*)d_in[6];
    const float* x   = (const float*)d_in[7];

    const float* W_m4 = (const float*)d_in[8];
    const float* g_m4 = (const float*)d_in[9];
    const float* b_m4 = (const float*)d_in[10];
    const float* W_i4 = (const float*)d_in[11];
    const float* g_i4 = (const float*)d_in[12];
    const float* b_i4 = (const float*)d_in[13];
    const float* W_m3 = (const float*)d_in[14];
    const float* g_m3 = (const float*)d_in[15];
    const float* b_m3 = (const float*)d_in[16];
    const float* W_i3 = (const float*)d_in[17];
    const float* g_i3 = (const float*)d_in[18];
    const float* b_i3 = (const float*)d_in[19];
    const float* W_m2 = (const float*)d_in[20];
    const float* g_m2 = (const float*)d_in[21];
    const float* b_m2 = (const float*)d_in[22];
    const float* W_i2 = (const float*)d_in[23];
    const float* g_i2 = (const float*)d_in[24];
    const float* b_i2 = (const float*)d_in[25];
    const float* W_m1 = (const float*)d_in[26];
    const float* g_m1 = (const float*)d_in[27];
    const float* b_m1 = (const float*)d_in[28];
    const float* W_c5 = (const float*)d_in[29];
    const float* g_c5 = (const float*)d_in[30];
    const float* b_c5 = (const float*)d_in[31];

    const int n4 = in_sizes[0] / 27;
    const int n3 = in_sizes[1] / 27;
    const int n2 = in_sizes[3] / 27;
    const int n1 = in_sizes[5] / 27;

    float *bufA, *bufB, *stats, *aff;
    cudaGetSymbolAddress((void**)&bufA, g_bufA);
    cudaGetSymbolAddress((void**)&bufB, g_bufB);
    cudaGetSymbolAddress((void**)&stats, g_stats);
    cudaGetSymbolAddress((void**)&aff, g_aff);

    // zero ALL 8*2*64 = 1024 stats entries (R3 fix: was <<<1,256>>>, left
    // layers 2-7 accumulating across graph replays)
    zero_stats_kernel<<<4, 256>>>();

    // L1: m4  (x -> A), 64->64, N=n4, identity prev
    gemm_gather_kernel<64, 64, 64, 64, 16, 4, false>
        <<<(n4 + 63) / 64, 256>>>(x, nbr4, W_m4, nullptr, bufA, stats + 0 * 128, n4);
    finalize_kernel<<<1, 64>>>(stats + 0 * 128, g_m4, b_m4, aff + 0 * 128, n4, 64);

    // L2: i4  (A -> B), 64->64, N=n3
    gemm_gather_kernel<64, 64, 64, 64, 16, 4, true>
        <<<(n3 + 63) / 64, 256>>>(bufA, inv43, W_i4, aff + 0 * 128, bufB, stats + 1 * 128, n3);
    finalize_kernel<<<1, 64>>>(stats + 1 * 128, g_i4, b_i4, aff + 1 * 128, n3, 64);

    // L3: m3  (B -> A), 64->64, N=n3
    gemm_gather_kernel<64, 64, 64, 64, 16, 4, true>
        <<<(n3 + 63) / 64, 256>>>(bufB, nbr3, W_m3, aff + 1 * 128, bufA, stats + 2 * 128, n3);
    finalize_kernel<<<1, 64>>>(stats + 2 * 128, g_m3, b_m3, aff + 2 * 128, n3, 64);

    // L4: i3  (A -> B), 64->32, N=n2
    gemm_gather_kernel<64, 32, 32, 64, 8, 2, true>
        <<<(n2 + 63) / 64, 256>>>(bufA, inv32, W_i3, aff + 2 * 128, bufB, stats + 3 * 128, n2);
    finalize_kernel<<<1, 64>>>(stats + 3 * 128, g_i3, b_i3, aff + 3 * 128, n2, 32);

    // L5: m2  (B -> A), 32->32, N=n2
    gemm_gather_kernel<32, 32, 32, 64, 8, 2, true>
        <<<(n2 + 63) / 64, 256>>>(bufB, nbr2, W_m2, aff + 3 * 128, bufA, stats + 4 * 128, n2);
    finalize_kernel<<<1, 64>>>(stats + 4 * 128, g_m2, b_m2, aff + 4 * 128, n2, 32);

    // L6: i2  (A -> B), 32->16, N=n1
    gemm_gather_kernel<32, 16, 16, 64, 4, 1, true>
        <<<(n1 + 63) / 64, 256>>>(bufA, inv21, W_i2, aff + 4 * 128, bufB, stats + 5 * 128, n1);
    finalize_kernel<<<1, 64>>>(stats + 5 * 128, g_i2, b_i2, aff + 5 * 128, n1, 16);

    // L7: m1  (B -> A), 16->16, N=n1
    gemm_gather_kernel<16, 16, 16, 64, 4, 1, true>
        <<<(n1 + 63) / 64, 256>>>(bufB, nbr1, W_m1, aff + 5 * 128, bufA, stats + 6 * 128, n1);
    finalize_kernel<<<1, 64>>>(stats + 6 * 128, g_m1, b_m1, aff + 6 * 128, n1, 16);

    // L8: c5  (A -> B raw), 16->3, N=n1, no relu on OUTPUT (relu applied to input here)
    gemm_gather_kernel<16, 3, 4, 256, 1, 1, true>
        <<<(n1 + 255) / 256, 256>>>(bufA, nbr1, W_c5, aff + 6 * 128, bufB, stats + 7 * 128, n1);
    finalize_kernel<<<1, 64>>>(stats + 7 * 128, g_c5, b_c5, aff + 7 * 128, n1, 3);

    // normalize final output (no relu)
    int total = n1 * 3;
    output_kernel<<<(total + 255) / 256, 256>>>(bufB, aff + 7 * 128, (float*)d_out, total);
}